// round 7
// baseline (speedup 1.0000x reference)
#include <cuda_runtime.h>
#include <cstdint>

// Problem dims (QuantLinearA8W8: M=4096, IN=4096, OUT=11008)
#define MDIM 4096
#define KDIM 4096
#define NDIM 11008

// Scratch (device globals — no allocation allowed in kernel_launch)
__device__ signed char g_qx8[(size_t)MDIM * KDIM];    // 16 MB: int8 activations
__device__ float       g_rowsum[MDIM];                // per-row sum of q
__device__ unsigned char g_w8[(size_t)NDIM * KDIM];   // 45 MB: int4 values 0..15 as bytes

// ---------------------------------------------------------------------------
// Kernel 1: quantize activations to int8 + per-row sum.
// ---------------------------------------------------------------------------
__global__ void quantize_kernel(const float* __restrict__ x,
                                const float* __restrict__ clampv, int K) {
    const int row = blockIdx.x;
    const int tid = threadIdx.x;
    const float cv  = __ldg(clampv);
    const float inv = 127.0f / cv;
    const float4* xr = reinterpret_cast<const float4*>(x + (size_t)row * K);
    uint32_t* qr = reinterpret_cast<uint32_t*>(g_qx8 + (size_t)row * K);
    float s = 0.0f;
    for (int i = tid; i < K / 4; i += blockDim.x) {
        float4 v = xr[i];
        int q0 = (int)rintf(fminf(fmaxf(v.x, -cv), cv) * inv);
        int q1 = (int)rintf(fminf(fmaxf(v.y, -cv), cv) * inv);
        int q2 = (int)rintf(fminf(fmaxf(v.z, -cv), cv) * inv);
        int q3 = (int)rintf(fminf(fmaxf(v.w, -cv), cv) * inv);
        s += (float)(q0 + q1 + q2 + q3);
        uint32_t w = (uint32_t)(q0 & 0xff) | ((uint32_t)(q1 & 0xff) << 8)
                   | ((uint32_t)(q2 & 0xff) << 16) | ((uint32_t)(q3 & 0xff) << 24);
        qr[i] = w;
    }
    __shared__ float red[256];
    red[tid] = s;
    __syncthreads();
    #pragma unroll
    for (int off = 128; off > 0; off >>= 1) {
        if (tid < off) red[tid] += red[tid + off];
        __syncthreads();
    }
    if (tid == 0) g_rowsum[row] = red[0];
}

// ---------------------------------------------------------------------------
// Kernel 2: unpack packed int4 (one byte per int32) to bytes 0..15.
// hi nibble -> even k, lo nibble -> odd k.
// ---------------------------------------------------------------------------
__global__ void unpack_kernel(const int* __restrict__ qw, long long ngroups) {
    long long i = (long long)blockIdx.x * blockDim.x + threadIdx.x;
    if (i >= ngroups) return;
    int4 w = __ldg(reinterpret_cast<const int4*>(qw) + i);
    unsigned long long r = 0;
    r |= (unsigned long long)((w.x >> 4) & 15);
    r |= (unsigned long long)(w.x & 15) << 8;
    r |= (unsigned long long)((w.y >> 4) & 15) << 16;
    r |= (unsigned long long)(w.y & 15) << 24;
    r |= (unsigned long long)((w.z >> 4) & 15) << 32;
    r |= (unsigned long long)(w.z & 15) << 40;
    r |= (unsigned long long)((w.w >> 4) & 15) << 48;
    r |= (unsigned long long)(w.w & 15) << 56;
    reinterpret_cast<unsigned long long*>(g_w8)[i] = r;
}

// ---------------------------------------------------------------------------
// Kernel 3: GEMM  C[m,n] = sum_k q[m,k] * v[n,k]   via int8 IMMA m16n8k32.
// ---------------------------------------------------------------------------
#define BM 128
#define BN 256
#define BK 64                                  // bytes of K per tile
#define PADB 80                                // bytes per smem row (stride 20 words: conflict-free)
#define STAGE_A (BM * PADB)                    // 10240 B
#define STAGE_B (BN * PADB)                    // 20480 B
#define SMEM_BYTES (2 * (STAGE_A + STAGE_B))   // 61440 B

__device__ __forceinline__ void cp_async16(void* sdst, const void* gsrc) {
    unsigned saddr = (unsigned)__cvta_generic_to_shared(sdst);
    asm volatile("cp.async.cg.shared.global [%0], [%1], 16;\n" :: "r"(saddr), "l"(gsrc));
}
__device__ __forceinline__ void cp_async_commit() { asm volatile("cp.async.commit_group;\n"); }
template <int N> __device__ __forceinline__ void cp_async_wait() {
    asm volatile("cp.async.wait_group %0;\n" :: "n"(N));
}

__device__ __forceinline__ void imma16832(int* c, const unsigned* a,
                                          unsigned b0, unsigned b1) {
    asm volatile(
        "mma.sync.aligned.m16n8k32.row.col.s32.s8.s8.s32 "
        "{%0,%1,%2,%3}, {%4,%5,%6,%7}, {%8,%9}, {%0,%1,%2,%3};\n"
        : "+r"(c[0]), "+r"(c[1]), "+r"(c[2]), "+r"(c[3])
        : "r"(a[0]), "r"(a[1]), "r"(a[2]), "r"(a[3]), "r"(b0), "r"(b1));
}

__global__ __launch_bounds__(256, 1)
void gemm_kernel(const float* __restrict__ scales, const int* __restrict__ qzeros,
                 const float* __restrict__ bias, const float* __restrict__ clampv,
                 float* __restrict__ out, int M, int N, int K) {
    extern __shared__ unsigned char smem[];
    unsigned char* As = smem;                       // [2][BM][PADB]
    unsigned char* Bs = smem + 2 * STAGE_A;         // [2][BN][PADB]

    const int tid = threadIdx.x;
    const int bm = blockIdx.y * BM;
    const int bn = blockIdx.x * BN;
    const signed char*   gA = g_qx8 + (size_t)bm * K;
    const unsigned char* gB = g_w8  + (size_t)bn * K;

    const int warp = tid >> 5, lane = tid & 31;
    const int wm = (warp >> 2) * 64;      // 2 warps along M
    const int wn = (warp & 3) * 64;       // 4 warps along N
    const int grp = lane >> 2, t4 = lane & 3;

    int acc[4][8][4];
    #pragma unroll
    for (int mi = 0; mi < 4; mi++)
        #pragma unroll
        for (int ni = 0; ni < 8; ni++)
            #pragma unroll
            for (int j = 0; j < 4; j++) acc[mi][ni][j] = 0;

    const int KT = K / BK;

    auto load_stage = [&](int st, int kt) {
        unsigned char* Ad = As + st * STAGE_A;
        unsigned char* Bd = Bs + st * STAGE_B;
        const signed char*   ga = gA + kt * BK;
        const unsigned char* gb = gB + kt * BK;
        #pragma unroll
        for (int i = 0; i < 2; i++) {              // A: 128 rows x 4 16B-chunks
            int c = tid + i * 256;
            int r = c >> 2, kc = c & 3;
            cp_async16(Ad + r * PADB + kc * 16, ga + (size_t)r * K + kc * 16);
        }
        #pragma unroll
        for (int i = 0; i < 4; i++) {              // B: 256 rows x 4 16B-chunks
            int c = tid + i * 256;
            int r = c >> 2, kc = c & 3;
            cp_async16(Bd + r * PADB + kc * 16, gb + (size_t)r * K + kc * 16);
        }
    };

    // prologue: two stages in flight
    load_stage(0, 0); cp_async_commit();
    if (KT > 1) { load_stage(1, 1); cp_async_commit(); }

    for (int kt = 0; kt < KT; kt++) {
        const int cur = kt & 1;
        if (kt + 1 < KT) cp_async_wait<1>(); else cp_async_wait<0>();
        __syncthreads();

        const unsigned char* Ab = As + cur * STAGE_A;
        const unsigned char* Bb = Bs + cur * STAGE_B;
        #pragma unroll
        for (int ks = 0; ks < 2; ks++) {
            const int kb = ks * 32;                // byte offset of this k32 step
            unsigned a[4][4];
            #pragma unroll
            for (int mi = 0; mi < 4; mi++) {
                const unsigned char* p = Ab + (wm + mi * 16 + grp) * PADB + kb + t4 * 4;
                a[mi][0] = *reinterpret_cast<const unsigned*>(p);
                a[mi][1] = *reinterpret_cast<const unsigned*>(p + 8 * PADB);
                a[mi][2] = *reinterpret_cast<const unsigned*>(p + 16);
                a[mi][3] = *reinterpret_cast<const unsigned*>(p + 8 * PADB + 16);
            }
            #pragma unroll
            for (int ni = 0; ni < 8; ni++) {
                const unsigned char* q = Bb + (wn + ni * 8 + grp) * PADB + kb + t4 * 4;
                unsigned b0 = *reinterpret_cast<const unsigned*>(q);
                unsigned b1 = *reinterpret_cast<const unsigned*>(q + 16);
                #pragma unroll
                for (int mi = 0; mi < 4; mi++)
                    imma16832(acc[mi][ni], a[mi], b0, b1);
            }
        }

        __syncthreads();
        if (kt + 2 < KT) {
            load_stage(cur, kt + 2);
            cp_async_commit();
        }
    }

    // ---- epilogue: out = a_scale*scale[n]*(acc - z[n]*rowsum[m]) + bias[n] ----
    const float cv = __ldg(clampv);
    const float a_scale = cv / 127.0f;
    float rs[4][2];
    #pragma unroll
    for (int mi = 0; mi < 4; mi++) {
        rs[mi][0] = g_rowsum[bm + wm + mi * 16 + grp];
        rs[mi][1] = g_rowsum[bm + wm + mi * 16 + grp + 8];
    }
    #pragma unroll
    for (int ni = 0; ni < 8; ni++) {
        const int c = bn + wn + ni * 8 + t4 * 2;
        const float s0 = a_scale * __ldg(scales + c);
        const float s1 = a_scale * __ldg(scales + c + 1);
        const float z0 = s0 * (float)__ldg(qzeros + c);
        const float z1 = s1 * (float)__ldg(qzeros + c + 1);
        const float b0 = __ldg(bias + c);
        const float b1 = __ldg(bias + c + 1);
        #pragma unroll
        for (int mi = 0; mi < 4; mi++) {
            const int r0 = bm + wm + mi * 16 + grp;
            float2 o0, o1;
            o0.x = s0 * (float)acc[mi][ni][0] - z0 * rs[mi][0] + b0;
            o0.y = s1 * (float)acc[mi][ni][1] - z1 * rs[mi][0] + b1;
            o1.x = s0 * (float)acc[mi][ni][2] - z0 * rs[mi][1] + b0;
            o1.y = s1 * (float)acc[mi][ni][3] - z1 * rs[mi][1] + b1;
            *reinterpret_cast<float2*>(out + (size_t)r0 * N + c)       = o0;
            *reinterpret_cast<float2*>(out + (size_t)(r0 + 8) * N + c) = o1;
        }
    }
}

// ---------------------------------------------------------------------------
extern "C" void kernel_launch(void* const* d_in, const int* in_sizes, int n_in,
                              void* d_out, int out_size) {
    const float* x      = (const float*)d_in[0];
    const int*   qw     = (const int*)  d_in[1];
    const int*   qz     = (const int*)  d_in[2];
    const float* scales = (const float*)d_in[3];
    const float* bias   = (const float*)d_in[4];
    const float* clampv = (const float*)d_in[5];

    const int OUT = in_sizes[2];                         // 11008
    const int IN  = (int)((2ll * in_sizes[1]) / OUT);    // 4096
    const int M   = (int)((long long)in_sizes[0] / IN);  // 4096

    quantize_kernel<<<M, 256>>>(x, clampv, IN);

    long long ngroups = (long long)OUT * IN / 8;
    unpack_kernel<<<(unsigned)((ngroups + 255) / 256), 256>>>(qw, ngroups);

    cudaFuncSetAttribute(gemm_kernel,
                         cudaFuncAttributeMaxDynamicSharedMemorySize, SMEM_BYTES);
    dim3 grid(OUT / BN, M / BM);   // 43 x 32
    gemm_kernel<<<grid, 256, SMEM_BYTES>>>(scales, qz, bias, clampv,
                                           (float*)d_out, M, OUT, IN);
}

// round 17
// speedup vs baseline: 2.4099x; 2.4099x over previous
#include <cuda_runtime.h>
#include <cuda_fp16.h>
#include <cstdint>

// Problem dims (QuantLinearA8W8: M=4096, IN=4096, OUT=11008)
#define MDIM 4096
#define KDIM 4096
#define NDIM 11008

// Scratch (device globals — no allocation allowed in kernel_launch)
__device__ __half g_qx[(size_t)MDIM * KDIM];     // 32 MB: int activations in f16
__device__ float  g_rowsum[MDIM];                // per-row sum of q
__device__ __half g_w16[(size_t)NDIM * KDIM];    // 90 MB: int4 values 0..15 as f16

// ---------------------------------------------------------------------------
// Kernel 1: quantize activations (exact integers in f16) + per-row sum.
// ---------------------------------------------------------------------------
__global__ void quantize_kernel(const float* __restrict__ x,
                                const float* __restrict__ clampv, int K) {
    const int row = blockIdx.x;
    const int tid = threadIdx.x;
    const float cv  = __ldg(clampv);
    const float inv = 127.0f / cv;
    const float4* xr = reinterpret_cast<const float4*>(x + (size_t)row * K);
    __half2* qr = reinterpret_cast<__half2*>(g_qx + (size_t)row * K);
    float s = 0.0f;
    for (int i = tid; i < K / 4; i += blockDim.x) {
        float4 v = xr[i];
        float q0 = rintf(fminf(fmaxf(v.x, -cv), cv) * inv);
        float q1 = rintf(fminf(fmaxf(v.y, -cv), cv) * inv);
        float q2 = rintf(fminf(fmaxf(v.z, -cv), cv) * inv);
        float q3 = rintf(fminf(fmaxf(v.w, -cv), cv) * inv);
        s += q0 + q1 + q2 + q3;
        qr[2 * i]     = __floats2half2_rn(q0, q1);
        qr[2 * i + 1] = __floats2half2_rn(q2, q3);
    }
    __shared__ float red[256];
    red[tid] = s;
    __syncthreads();
    #pragma unroll
    for (int off = 128; off > 0; off >>= 1) {
        if (tid < off) red[tid] += red[tid + off];
        __syncthreads();
    }
    if (tid == 0) g_rowsum[row] = red[0];
}

// ---------------------------------------------------------------------------
// Kernel 2: unpack int4 (one byte per int32) to f16 values 0..15.
// hi nibble -> even k, lo nibble -> odd k.  (0x6400|n) = half(1024+n).
// ---------------------------------------------------------------------------
__device__ __forceinline__ unsigned nib2h2(int v) {
    const __half2 off = __halves2half2(__ushort_as_half(0x6400), __ushort_as_half(0x6400));
    unsigned p = 0x64006400u | ((unsigned)(v >> 4) & 15u) | (((unsigned)v & 15u) << 16);
    __half2 h = __hsub2(*reinterpret_cast<__half2*>(&p), off);
    return *reinterpret_cast<unsigned*>(&h);
}

__global__ void unpack_f16_kernel(const int* __restrict__ qw, long long nvec) {
    long long i = (long long)blockIdx.x * blockDim.x + threadIdx.x;
    if (i >= nvec) return;
    int4 w = __ldg(reinterpret_cast<const int4*>(qw) + i);
    uint4 o;
    o.x = nib2h2(w.x);
    o.y = nib2h2(w.y);
    o.z = nib2h2(w.z);
    o.w = nib2h2(w.w);
    reinterpret_cast<uint4*>(g_w16)[i] = o;
}

// ---------------------------------------------------------------------------
// Kernel 3: f16 HMMA GEMM, ldmatrix fragments, 3-stage cp.async, 1 sync/K-tile.
// ---------------------------------------------------------------------------
#define BM 128
#define BN 256
#define BK 64
#define ROWB 144                                // bytes per smem row (72 halves; conflict-free)
#define STAGE_A (BM * ROWB)                     // 18432 B
#define STAGE_B (BN * ROWB)                     // 36864 B
#define STAGE_SZ (STAGE_A + STAGE_B)            // 55296 B
#define SMEM_BYTES (3 * STAGE_SZ)               // 165888 B

__device__ __forceinline__ void cp_async16(uint32_t sdst, const void* gsrc) {
    asm volatile("cp.async.cg.shared.global [%0], [%1], 16;\n" :: "r"(sdst), "l"(gsrc));
}
__device__ __forceinline__ void cp_commit() { asm volatile("cp.async.commit_group;\n"); }
template <int N> __device__ __forceinline__ void cp_wait() {
    asm volatile("cp.async.wait_group %0;\n" :: "n"(N));
}
__device__ __forceinline__ void ldsm4(unsigned* r, uint32_t addr) {
    asm volatile("ldmatrix.sync.aligned.m8n8.x4.shared.b16 {%0,%1,%2,%3}, [%4];"
                 : "=r"(r[0]), "=r"(r[1]), "=r"(r[2]), "=r"(r[3]) : "r"(addr));
}
__device__ __forceinline__ void mma16816(float* c, const unsigned* a,
                                         unsigned b0, unsigned b1) {
    asm volatile(
        "mma.sync.aligned.m16n8k16.row.col.f32.f16.f16.f32 "
        "{%0,%1,%2,%3}, {%4,%5,%6,%7}, {%8,%9}, {%0,%1,%2,%3};\n"
        : "+f"(c[0]), "+f"(c[1]), "+f"(c[2]), "+f"(c[3])
        : "r"(a[0]), "r"(a[1]), "r"(a[2]), "r"(a[3]), "r"(b0), "r"(b1));
}

__global__ __launch_bounds__(256, 1)
void gemm_kernel(const float* __restrict__ scales, const int* __restrict__ qzeros,
                 const float* __restrict__ bias, const float* __restrict__ clampv,
                 float* __restrict__ out, int M, int N, int K) {
    extern __shared__ unsigned char smem[];
    uint32_t sb;
    asm("{ .reg .u64 t; cvta.to.shared.u64 t, %1; cvt.u32.u64 %0, t; }" : "=r"(sb) : "l"(smem));

    const int tid = threadIdx.x;
    const int bm = blockIdx.y * BM;
    const int bn = blockIdx.x * BN;
    const __half* gA = g_qx  + (size_t)bm * K;
    const __half* gB = g_w16 + (size_t)bn * K;

    const int warp = tid >> 5, lane = tid & 31;
    const int wm = (warp >> 2) * 64;      // 2 warps along M
    const int wn = (warp & 3) * 64;       // 4 warps along N

    // ldmatrix per-lane source rows/cols
    const int aRow = wm + (lane & 15);
    const int aCol = (lane >> 4) * 16;                        // bytes
    const int bRow = wn + (lane & 7) + ((lane & 16) >> 1);
    const int bCol = ((lane >> 3) & 1) * 16;                  // bytes

    float acc[4][8][4];
    #pragma unroll
    for (int mi = 0; mi < 4; mi++)
        #pragma unroll
        for (int ni = 0; ni < 8; ni++)
            #pragma unroll
            for (int j = 0; j < 4; j++) acc[mi][ni][j] = 0.0f;

    const int KT = K / BK;

    auto load_stage = [&](int st, int kt) {
        const uint32_t Ad = sb + st * STAGE_SZ;
        const uint32_t Bd = Ad + STAGE_A;
        const __half* ga = gA + kt * BK;
        const __half* gb = gB + kt * BK;
        #pragma unroll
        for (int i = 0; i < 4; i++) {               // A: 128 rows x 8 chunks
            int c = tid + i * 256;
            int r = c >> 3, kc = c & 7;
            cp_async16(Ad + r * ROWB + kc * 16, ga + (size_t)r * K + kc * 8);
        }
        #pragma unroll
        for (int i = 0; i < 8; i++) {               // B: 256 rows x 8 chunks
            int c = tid + i * 256;
            int r = c >> 3, kc = c & 7;
            cp_async16(Bd + r * ROWB + kc * 16, gb + (size_t)r * K + kc * 8);
        }
    };

    load_stage(0, 0); cp_commit();
    if (KT > 1) { load_stage(1, 1); cp_commit(); }

    for (int kt = 0; kt < KT; kt++) {
        const int cur = kt % 3;
        if (kt + 1 < KT) cp_wait<1>(); else cp_wait<0>();
        __syncthreads();

        if (kt + 2 < KT) {               // refill slot consumed at kt-1 (sync-guarded)
            load_stage((kt + 2) % 3, kt + 2);
            cp_commit();
        }

        const uint32_t Ab = sb + cur * STAGE_SZ;
        const uint32_t Bb = Ab + STAGE_A;
        #pragma unroll
        for (int ks = 0; ks < 4; ks++) {
            const int kb = ks * 32;      // byte offset of this k16 step
            unsigned a[4][4], b[4][4];
            #pragma unroll
            for (int mi = 0; mi < 4; mi++)
                ldsm4(a[mi], Ab + (aRow + mi * 16) * ROWB + kb + aCol);
            #pragma unroll
            for (int p = 0; p < 4; p++)
                ldsm4(b[p], Bb + (bRow + p * 16) * ROWB + kb + bCol);
            #pragma unroll
            for (int p = 0; p < 4; p++) {
                #pragma unroll
                for (int mi = 0; mi < 4; mi++) {
                    mma16816(acc[mi][2 * p],     a[mi], b[p][0], b[p][1]);
                    mma16816(acc[mi][2 * p + 1], a[mi], b[p][2], b[p][3]);
                }
            }
        }
    }

    // ---- epilogue: out = a_scale*scale[n]*(acc - z[n]*rowsum[m]) + bias[n] ----
    const int grp = lane >> 2, t4 = lane & 3;
    const float cv = __ldg(clampv);
    const float a_scale = cv / 127.0f;
    float rs[4][2];
    #pragma unroll
    for (int mi = 0; mi < 4; mi++) {
        rs[mi][0] = g_rowsum[bm + wm + mi * 16 + grp];
        rs[mi][1] = g_rowsum[bm + wm + mi * 16 + grp + 8];
    }
    #pragma unroll
    for (int ni = 0; ni < 8; ni++) {
        const int c = bn + wn + ni * 8 + t4 * 2;
        const float s0 = a_scale * __ldg(scales + c);
        const float s1 = a_scale * __ldg(scales + c + 1);
        const float z0 = s0 * (float)__ldg(qzeros + c);
        const float z1 = s1 * (float)__ldg(qzeros + c + 1);
        const float b0 = __ldg(bias + c);
        const float b1 = __ldg(bias + c + 1);
        #pragma unroll
        for (int mi = 0; mi < 4; mi++) {
            const int r0 = bm + wm + mi * 16 + grp;
            float2 o0, o1;
            o0.x = s0 * acc[mi][ni][0] - z0 * rs[mi][0] + b0;
            o0.y = s1 * acc[mi][ni][1] - z1 * rs[mi][0] + b1;
            o1.x = s0 * acc[mi][ni][2] - z0 * rs[mi][1] + b0;
            o1.y = s1 * acc[mi][ni][3] - z1 * rs[mi][1] + b1;
            *reinterpret_cast<float2*>(out + (size_t)r0 * N + c)       = o0;
            *reinterpret_cast<float2*>(out + (size_t)(r0 + 8) * N + c) = o1;
        }
    }
}

// ---------------------------------------------------------------------------
extern "C" void kernel_launch(void* const* d_in, const int* in_sizes, int n_in,
                              void* d_out, int out_size) {
    const float* x      = (const float*)d_in[0];
    const int*   qw     = (const int*)  d_in[1];
    const int*   qz     = (const int*)  d_in[2];
    const float* scales = (const float*)d_in[3];
    const float* bias   = (const float*)d_in[4];
    const float* clampv = (const float*)d_in[5];

    const int OUT = in_sizes[2];                         // 11008
    const int IN  = (int)((2ll * in_sizes[1]) / OUT);    // 4096
    const int M   = (int)((long long)in_sizes[0] / IN);  // 4096

    quantize_kernel<<<M, 256>>>(x, clampv, IN);

    long long nvec = (long long)OUT * IN / 8;
    unpack_f16_kernel<<<(unsigned)((nvec + 255) / 256), 256>>>(qw, nvec);

    cudaFuncSetAttribute(gemm_kernel,
                         cudaFuncAttributeMaxDynamicSharedMemorySize, SMEM_BYTES);
    dim3 grid(OUT / BN, M / BM);   // 43 x 32
    gemm_kernel<<<grid, 256, SMEM_BYTES>>>(scales, qz, bias, clampv,
                                           (float*)d_out, M, OUT, IN);
}